// round 13
// baseline (speedup 1.0000x reference)
#include <cuda_runtime.h>
#include <cuda_bf16.h>

// Problem constants (fixed by dataset): N = 131072 neurons, E = N*64 edges.
#define MAX_N 131072
#define NWORDS (MAX_N / 32)     // 4096 words = 16 KB per bitmask

// Scratch: zero-initialized at load; neuron kernel consumes AND re-zeros so
// every graph replay starts clean (deterministic).
// Packed event counts: low 16 bits = excitatory arrivals, high 16 = inhibitory.
__device__ unsigned int g_cnt[MAX_N];
// Bit-planar spike tables: 1 bit/neuron.
__device__ unsigned int g_act[NWORDS];   // neuron spiked last step
__device__ unsigned int g_exc[NWORDS];   // spiked AND excitatory

// Generation-monotonic grid barrier (counters only grow across graph replays;
// behavior is replay-invariant).
__device__ unsigned int          g_bar_cnt;
__device__ volatile unsigned int g_bar_rel;

// ---------------------------------------------------------------------------
// Kernel 1 (fused mask + scatter): each block builds the spike bitmask for its
// 512-neuron slice, front-batches round-0 src int4 loads (34 MB src stream
// drains during mask build + barrier), passes a one-shot grid barrier, stages
// the 16 KB act + 16 KB exc bitmasks to smem, then runs the edge loop:
// bit-test every edge, int4 dst load only for groups with an active source,
// one packed-int atomic per active edge (no value gather).
// Deadlock safety: grid = E/32768 = 256 blocks <= 296 co-resident slots at
// 2 CTAs/SM (launch_bounds forces regs <= 32, smem 32 KB).
// ---------------------------------------------------------------------------
#define EDGE_BLOCK  1024
#define EDGE_GPT    4                               // int4 groups per round
#define EDGE_ROUNDS 2
#define EDGE_PER_BLOCK (EDGE_BLOCK * EDGE_GPT * 4 * EDGE_ROUNDS)  // 32768

__global__ void __launch_bounds__(EDGE_BLOCK, 2)
edge_kernel(const float* __restrict__ spiked,
            const float* __restrict__ is_exc,
            const int* __restrict__ src,
            const int* __restrict__ dst,
            int n, int E) {
    __shared__ unsigned int s_act[NWORDS];   // 16 KB
    __shared__ unsigned int s_exc[NWORDS];   // 16 KB

    const int tid = threadIdx.x;
    long base = (long)blockIdx.x * EDGE_PER_BLOCK;
    bool full = (base + EDGE_PER_BLOCK) <= (long)E;

    const int4* src4 = reinterpret_cast<const int4*>(src + base);
    const int4* dst4 = reinterpret_cast<const int4*>(dst + base);

    // ---- phase 1a: issue mask loads FIRST (they return before src batch) ----
    float spv = 0.0f, exv = 0.0f;
    int i0 = blockIdx.x * 512 + tid;
    bool in0 = (tid < 512) && (i0 < n);
    if (in0) {
        spv = spiked[i0];
        exv = is_exc[i0];
    }

    // ---- phase 1b: front-batch round-0 src (independent, long-latency) ----
    int4 sb[EDGE_GPT];
    if (full) {
#pragma unroll
        for (int k = 0; k < EDGE_GPT; k++)
            sb[k] = src4[tid + k * EDGE_BLOCK];
    }

    // ---- phase 1c: ballots + mask stores ----
    if (tid < 512) {
        bool sp = in0 && (spv != 0.0f);
        unsigned int act = __ballot_sync(0xffffffffu, sp);
        unsigned int exc = __ballot_sync(0xffffffffu, sp && (exv != 0.0f));
        if ((tid & 31) == 0 && in0) {
            g_act[i0 >> 5] = act;
            g_exc[i0 >> 5] = exc;
        }
    }
    // rare: extra slices if grid < ceil(n/512) (not hit for this dataset)
    for (int s = blockIdx.x + gridDim.x; s * 512 < n; s += gridDim.x) {
        int i = s * 512 + tid;
        if (tid < 512) {
            bool in = i < n;
            bool sp = in && (spiked[i] != 0.0f);
            unsigned int act = __ballot_sync(0xffffffffu, sp);
            unsigned int exc = __ballot_sync(0xffffffffu, sp && (is_exc[i] != 0.0f));
            if ((tid & 31) == 0 && in) {
                g_act[i >> 5] = act;
                g_exc[i >> 5] = exc;
            }
        }
    }

    // ---- phase 2: one-shot grid barrier (generation-monotonic) ----
    __syncthreads();
    if (tid == 0) {
        __threadfence();
        unsigned int t = atomicAdd(&g_bar_cnt, 1u);
        unsigned int gen = t / gridDim.x;
        if ((t % gridDim.x) == gridDim.x - 1u) {
            g_bar_rel = gen + 1u;
        } else {
            while (g_bar_rel < gen + 1u) { }
        }
    }
    __syncthreads();
    __threadfence();

    // ---- phase 3: stage tables (L2-coherent loads; L1 flushed per launch) ----
    {
        const uint4* ga = reinterpret_cast<const uint4*>(g_act);
        const uint4* gx = reinterpret_cast<const uint4*>(g_exc);
        reinterpret_cast<uint4*>(s_act)[tid] = __ldcg(ga + tid);
        reinterpret_cast<uint4*>(s_exc)[tid] = __ldcg(gx + tid);
    }
    __syncthreads();

    // ---- phase 4: edge loop (R9-proven) ----
    if (full) {
#pragma unroll
        for (int r = 0; r < EDGE_ROUNDS; r++) {
            if (r > 0) {
#pragma unroll
                for (int k = 0; k < EDGE_GPT; k++)
                    sb[k] = src4[tid + (r * EDGE_GPT + k) * EDGE_BLOCK];
            }
#pragma unroll
            for (int k = 0; k < EDGE_GPT; k++) {
                int ss[4] = {sb[k].x, sb[k].y, sb[k].z, sb[k].w};
                unsigned int aa[4];
                unsigned int any = 0;
#pragma unroll
                for (int j = 0; j < 4; j++) {
                    aa[j] = (s_act[ss[j] >> 5] >> (ss[j] & 31)) & 1u;
                    any |= aa[j];
                }
                if (any) {
                    int4 d4 = dst4[tid + (r * EDGE_GPT + k) * EDGE_BLOCK];
                    int dd[4] = {d4.x, d4.y, d4.z, d4.w};
#pragma unroll
                    for (int j = 0; j < 4; j++) {
                        if (aa[j]) {
                            int idx = ss[j];
                            bool e = (s_exc[idx >> 5] >> (idx & 31)) & 1u;
                            atomicAdd(&g_cnt[dd[j]], e ? 1u : 65536u);
                        }
                    }
                }
            }
        }
    } else {
        for (long e = base + tid; e < E; e += EDGE_BLOCK) {
            int idx = src[e];
            if ((s_act[idx >> 5] >> (idx & 31)) & 1u) {
                bool ex = (s_exc[idx >> 5] >> (idx & 31)) & 1u;
                atomicAdd(&g_cnt[dst[e]], ex ? 1u : 65536u);
            }
        }
    }
}

// ---------------------------------------------------------------------------
// Kernel 2: AdEx neuron update, float4-vectorized (PDL secondary of edge).
// All parameter streams are loaded BEFORE the dependency sync; only the
// packed-count consumption waits for the edge atomics.
// ge += Q_ge * exc_count ; gi += Q_gi * inh_count  (Q read coalesced here).
// ---------------------------------------------------------------------------
__global__ void neuron_kernel(
    const float4* __restrict__ voltage, const float4* __restrict__ adapt,
    const float4* __restrict__ ge_in,   const float4* __restrict__ gi_in,
    const float4* __restrict__ stim,    const float4* __restrict__ refr_in,
    const float4* __restrict__ g_L,     const float4* __restrict__ delta_T,
    const float4* __restrict__ v_thresh,const float4* __restrict__ v_rest,
    const float4* __restrict__ Cm,      const float4* __restrict__ aa,
    const float4* __restrict__ bb,      const float4* __restrict__ tau_w,
    const float4* __restrict__ tau_ge,  const float4* __restrict__ tau_gi,
    const float4* __restrict__ E_ge,    const float4* __restrict__ E_gi,
    const float4* __restrict__ I_bias,  const float4* __restrict__ stim_scale,
    const float4* __restrict__ Qge,     const float4* __restrict__ Qgi,
    const float4* __restrict__ v_cut,   const float4* __restrict__ v_reset,
    const float4* __restrict__ t_refrac,
    const float* __restrict__ dt_ptr,
    float* __restrict__ out, int n4) {
    int i = blockIdx.x * blockDim.x + threadIdx.x;
    if (i >= n4) { cudaGridDependencySynchronize(); return; }
    int n = n4 * 4;

    // ---- pre-dependency loads (independent of edge kernel output) ----
    float dt = __ldg(dt_ptr);
    float4 v4  = voltage[i];
    float4 w4  = adapt[i];
    float4 ge4 = ge_in[i];
    float4 gi4 = gi_in[i];
    float4 Qe4 = Qge[i];
    float4 Qi4 = Qgi[i];
    float4 gl4 = g_L[i];
    float4 dT4 = delta_T[i];
    float4 vt4 = v_thresh[i];
    float4 vr4 = v_rest[i];
    float4 C4  = Cm[i];
    float4 a4  = aa[i];
    float4 b4  = bb[i];
    float4 tw4 = tau_w[i];
    float4 tge4 = tau_ge[i];
    float4 tgi4 = tau_gi[i];
    float4 Ege4 = E_ge[i];
    float4 Egi4 = E_gi[i];
    float4 Ib4  = I_bias[i];
    float4 ssc4 = stim_scale[i];
    float4 st4  = stim[i];
    float4 vc4  = v_cut[i];
    float4 vrs4 = v_reset[i];
    float4 tr4  = t_refrac[i];
    float4 rf4  = refr_in[i];

    // ---- wait for edge atomics, then consume + re-zero counts ----
    cudaGridDependencySynchronize();
    uint4 c4 = *reinterpret_cast<const uint4*>(g_cnt + i * 4);
    *reinterpret_cast<uint4*>(g_cnt + i * 4) = make_uint4(0u, 0u, 0u, 0u);
    unsigned int cl[4] = {c4.x, c4.y, c4.z, c4.w};

    float4 vo, wo, geo, gio, ro, so;
    int lane = 0;

#define LANE(F)                                                                 \
    {                                                                           \
        unsigned int cnt = cl[lane++];                                          \
        float v = v4.F, w = w4.F;                                               \
        float ge = ge4.F + Qe4.F * (float)(cnt & 0xffffu);                      \
        float gi = gi4.F + Qi4.F * (float)(cnt >> 16);                          \
        float gl = gl4.F, dT = dT4.F, vr = vr4.F;                               \
        float I = Ib4.F + ssc4.F * st4.F + ge * (Ege4.F - v) + gi * (Egi4.F - v); \
        float exp_term = gl * dT * expf(fminf((v - vt4.F) / dT, 20.0f));        \
        float dv = (-gl * (v - vr) + exp_term - w + I) / C4.F;                  \
        float dw = (-w + a4.F * (v - vr)) / tw4.F;                              \
        float refr = rf4.F;                                                     \
        float vn = (refr <= 0.0f) ? (v + dv * dt) : v;                          \
        float wn = w + dw * dt;                                                 \
        geo.F = ge - (ge / tge4.F) * dt;                                        \
        gio.F = gi - (gi / tgi4.F) * dt;                                        \
        bool spk = vn > vc4.F;                                                  \
        vo.F = spk ? vrs4.F : vn;                                               \
        wo.F = spk ? (wn + b4.F) : wn;                                          \
        ro.F = (spk ? tr4.F : refr) - dt;                                       \
        so.F = spk ? 1.0f : 0.0f;                                               \
    }
    LANE(x) LANE(y) LANE(z) LANE(w)
#undef LANE

    *reinterpret_cast<float4*>(out + 0 * n + i * 4) = vo;
    *reinterpret_cast<float4*>(out + 1 * n + i * 4) = wo;
    *reinterpret_cast<float4*>(out + 2 * n + i * 4) = geo;
    *reinterpret_cast<float4*>(out + 3 * n + i * 4) = gio;
    *reinterpret_cast<float4*>(out + 4 * n + i * 4) = ro;
    *reinterpret_cast<float4*>(out + 5 * n + i * 4) = so;
}

extern "C" void kernel_launch(void* const* d_in, const int* in_sizes, int n_in,
                              void* d_out, int out_size) {
    const float* voltage    = (const float*)d_in[0];
    const float* adapt      = (const float*)d_in[1];
    const float* ge         = (const float*)d_in[2];
    const float* gi         = (const float*)d_in[3];
    const float* stim       = (const float*)d_in[4];
    const float* refr       = (const float*)d_in[5];
    const float* g_L        = (const float*)d_in[6];
    const float* delta_T    = (const float*)d_in[7];
    const float* v_thresh   = (const float*)d_in[8];
    const float* v_rest     = (const float*)d_in[9];
    const float* C          = (const float*)d_in[10];
    const float* a          = (const float*)d_in[11];
    const float* b          = (const float*)d_in[12];
    const float* tau_w      = (const float*)d_in[13];
    const float* tau_ge     = (const float*)d_in[14];
    const float* tau_gi     = (const float*)d_in[15];
    const float* E_ge       = (const float*)d_in[16];
    const float* E_gi       = (const float*)d_in[17];
    const float* I_bias     = (const float*)d_in[18];
    const float* stim_scale = (const float*)d_in[19];
    const float* Q_ge       = (const float*)d_in[20];
    const float* Q_gi       = (const float*)d_in[21];
    const float* v_cut      = (const float*)d_in[22];
    const float* v_reset    = (const float*)d_in[23];
    const float* t_refrac   = (const float*)d_in[24];
    const float* spiked     = (const float*)d_in[25];
    const float* is_exc     = (const float*)d_in[26];
    const int*   edge_index = (const int*)d_in[27];
    const float* dt         = (const float*)d_in[28];

    int n = in_sizes[0];
    int n4 = n / 4;
    int E = in_sizes[27] / 2;
    const int* src = edge_index;
    const int* dst = edge_index + E;

    {
        int edge_blocks = (E + EDGE_PER_BLOCK - 1) / EDGE_PER_BLOCK;  // 256
        edge_kernel<<<edge_blocks, EDGE_BLOCK>>>(spiked, is_exc, src, dst, n, E);
    }

    // PDL attribute: neuron may launch before edge completes; ordering is
    // enforced by cudaGridDependencySynchronize() inside the kernel.
    cudaLaunchAttribute pdl[1];
    pdl[0].id = cudaLaunchAttributeProgrammaticStreamSerialization;
    pdl[0].val.programmaticStreamSerializationAllowed = 1;

    {
        cudaLaunchConfig_t cfg = {};
        cfg.gridDim  = dim3((n4 + 63) / 64, 1, 1);
        cfg.blockDim = dim3(64, 1, 1);
        cfg.attrs = pdl;
        cfg.numAttrs = 1;
        cudaLaunchKernelEx(&cfg, neuron_kernel,
            (const float4*)voltage, (const float4*)adapt,
            (const float4*)ge, (const float4*)gi,
            (const float4*)stim, (const float4*)refr,
            (const float4*)g_L, (const float4*)delta_T,
            (const float4*)v_thresh, (const float4*)v_rest,
            (const float4*)C, (const float4*)a, (const float4*)b,
            (const float4*)tau_w, (const float4*)tau_ge, (const float4*)tau_gi,
            (const float4*)E_ge, (const float4*)E_gi,
            (const float4*)I_bias, (const float4*)stim_scale,
            (const float4*)Q_ge, (const float4*)Q_gi,
            (const float4*)v_cut, (const float4*)v_reset, (const float4*)t_refrac,
            dt, (float*)d_out, n4);
    }
}

// round 14
// speedup vs baseline: 1.1001x; 1.1001x over previous
#include <cuda_runtime.h>
#include <cuda_bf16.h>

// Problem constants (fixed by dataset): N = 131072 neurons, E = N*64 edges.
#define MAX_N 131072
#define NWORDS (MAX_N / 32)     // 4096 words = 16 KB per bitmask

// Scratch: zero-initialized at load; neuron kernel consumes AND re-zeros so
// every graph replay starts clean (deterministic).
// Packed event counts: low 16 bits = excitatory arrivals, high 16 = inhibitory.
__device__ unsigned int g_cnt[MAX_N];
// Bit-planar spike tables: 1 bit/neuron.
__device__ unsigned int g_act[NWORDS];   // neuron spiked last step
__device__ unsigned int g_exc[NWORDS];   // spiked AND excitatory

// ---------------------------------------------------------------------------
// Kernel 1: build bitmasks. 1 neuron/thread, warp ballots, lane 0 writes.
// Bool inputs arrive as float32 (0.0 / 1.0).
// ---------------------------------------------------------------------------
__global__ void build_mask_kernel(const float* __restrict__ spiked,
                                  const float* __restrict__ is_exc,
                                  int n) {
    int i = blockIdx.x * blockDim.x + threadIdx.x;
    if (i >= n) return;
    bool s = spiked[i] != 0.0f;
    bool x = is_exc[i] != 0.0f;
    unsigned int act = __ballot_sync(0xffffffffu, s);
    unsigned int exc = __ballot_sync(0xffffffffu, s && x);
    if ((i & 31) == 0) {
        g_act[i >> 5] = act;
        g_exc[i >> 5] = exc;
    }
}

// ---------------------------------------------------------------------------
// Kernel 2: event-driven synaptic scatter (PDL secondary of build_mask).
// 32768 edges/block in 2 rounds of 4 int4 src groups/thread. Round-0 src is
// front-batched BEFORE cudaGridDependencySynchronize to overlap the build
// kernel. 16 KB act + 16 KB exc bitmasks staged in smem; dst int4 loaded only
// for groups with an active source; one packed-int atomic per active edge.
// ---------------------------------------------------------------------------
#define EDGE_BLOCK  1024
#define EDGE_GPT    4                               // int4 groups per round
#define EDGE_ROUNDS 2
#define EDGE_PER_BLOCK (EDGE_BLOCK * EDGE_GPT * 4 * EDGE_ROUNDS)  // 32768

__global__ void __launch_bounds__(EDGE_BLOCK, 2)
edge_kernel(const int* __restrict__ src,
            const int* __restrict__ dst,
            int E) {
    __shared__ unsigned int s_act[NWORDS];   // 16 KB
    __shared__ unsigned int s_exc[NWORDS];   // 16 KB

    const int tid = threadIdx.x;
    long base = (long)blockIdx.x * EDGE_PER_BLOCK;
    bool full = (base + EDGE_PER_BLOCK) <= (long)E;

    const int4* src4 = reinterpret_cast<const int4*>(src + base);
    const int4* dst4 = reinterpret_cast<const int4*>(dst + base);

    // ---- pre-dependency: front-batch round-0 src (independent of build) ----
    int4 sb[EDGE_GPT];
    if (full) {
#pragma unroll
        for (int k = 0; k < EDGE_GPT; k++)
            sb[k] = src4[tid + k * EDGE_BLOCK];
    }

    // ---- wait for build_mask results, then stage tables ----
    cudaGridDependencySynchronize();
    {
        const uint4* ga = reinterpret_cast<const uint4*>(g_act);
        const uint4* gx = reinterpret_cast<const uint4*>(g_exc);
        reinterpret_cast<uint4*>(s_act)[tid] = ga[tid];
        reinterpret_cast<uint4*>(s_exc)[tid] = gx[tid];
    }
    __syncthreads();

    if (full) {
#pragma unroll
        for (int r = 0; r < EDGE_ROUNDS; r++) {
            if (r > 0) {
#pragma unroll
                for (int k = 0; k < EDGE_GPT; k++)
                    sb[k] = src4[tid + (r * EDGE_GPT + k) * EDGE_BLOCK];
            }
#pragma unroll
            for (int k = 0; k < EDGE_GPT; k++) {
                int ss[4] = {sb[k].x, sb[k].y, sb[k].z, sb[k].w};
                unsigned int aa[4];
                unsigned int any = 0;
#pragma unroll
                for (int j = 0; j < 4; j++) {
                    aa[j] = (s_act[ss[j] >> 5] >> (ss[j] & 31)) & 1u;
                    any |= aa[j];
                }
                if (any) {
                    int4 d4 = dst4[tid + (r * EDGE_GPT + k) * EDGE_BLOCK];
                    int dd[4] = {d4.x, d4.y, d4.z, d4.w};
#pragma unroll
                    for (int j = 0; j < 4; j++) {
                        if (aa[j]) {
                            int idx = ss[j];
                            bool e = (s_exc[idx >> 5] >> (idx & 31)) & 1u;
                            atomicAdd(&g_cnt[dd[j]], e ? 1u : 65536u);
                        }
                    }
                }
            }
        }
    } else {
        for (long e = base + tid; e < E; e += EDGE_BLOCK) {
            int idx = src[e];
            if ((s_act[idx >> 5] >> (idx & 31)) & 1u) {
                bool ex = (s_exc[idx >> 5] >> (idx & 31)) & 1u;
                atomicAdd(&g_cnt[dst[e]], ex ? 1u : 65536u);
            }
        }
    }
}

// ---------------------------------------------------------------------------
// Kernel 3: AdEx neuron update, float4-vectorized (PDL secondary of edge).
// Dependency sync FIRST (no state held across it -> low regs, high occupancy;
// PDL still hides launch latency: blocks reach the sync during the edge tail).
// ge += Q_ge * exc_count ; gi += Q_gi * inh_count  (Q read coalesced here).
// ---------------------------------------------------------------------------
__global__ void __launch_bounds__(128, 8)
neuron_kernel(
    const float4* __restrict__ voltage, const float4* __restrict__ adapt,
    const float4* __restrict__ ge_in,   const float4* __restrict__ gi_in,
    const float4* __restrict__ stim,    const float4* __restrict__ refr_in,
    const float4* __restrict__ g_L,     const float4* __restrict__ delta_T,
    const float4* __restrict__ v_thresh,const float4* __restrict__ v_rest,
    const float4* __restrict__ Cm,      const float4* __restrict__ aa,
    const float4* __restrict__ bb,      const float4* __restrict__ tau_w,
    const float4* __restrict__ tau_ge,  const float4* __restrict__ tau_gi,
    const float4* __restrict__ E_ge,    const float4* __restrict__ E_gi,
    const float4* __restrict__ I_bias,  const float4* __restrict__ stim_scale,
    const float4* __restrict__ Qge,     const float4* __restrict__ Qgi,
    const float4* __restrict__ v_cut,   const float4* __restrict__ v_reset,
    const float4* __restrict__ t_refrac,
    const float* __restrict__ dt_ptr,
    float* __restrict__ out, int n4) {
    // wait for edge atomics up front -> nothing held across the sync
    cudaGridDependencySynchronize();

    int i = blockIdx.x * blockDim.x + threadIdx.x;
    if (i >= n4) return;
    int n = n4 * 4;

    float dt = __ldg(dt_ptr);

    uint4 c4 = *reinterpret_cast<const uint4*>(g_cnt + i * 4);
    *reinterpret_cast<uint4*>(g_cnt + i * 4) = make_uint4(0u, 0u, 0u, 0u);
    unsigned int cl[4] = {c4.x, c4.y, c4.z, c4.w};

    float4 v4  = voltage[i];
    float4 w4  = adapt[i];
    float4 ge4 = ge_in[i];
    float4 gi4 = gi_in[i];
    float4 Qe4 = Qge[i];
    float4 Qi4 = Qgi[i];
    float4 gl4 = g_L[i];
    float4 dT4 = delta_T[i];
    float4 vt4 = v_thresh[i];
    float4 vr4 = v_rest[i];
    float4 C4  = Cm[i];
    float4 a4  = aa[i];
    float4 b4  = bb[i];
    float4 tw4 = tau_w[i];
    float4 tge4 = tau_ge[i];
    float4 tgi4 = tau_gi[i];
    float4 Ege4 = E_ge[i];
    float4 Egi4 = E_gi[i];
    float4 Ib4  = I_bias[i];
    float4 ssc4 = stim_scale[i];
    float4 st4  = stim[i];
    float4 vc4  = v_cut[i];
    float4 vrs4 = v_reset[i];
    float4 tr4  = t_refrac[i];
    float4 rf4  = refr_in[i];

    float4 vo, wo, geo, gio, ro, so;
    int lane = 0;

#define LANE(F)                                                                 \
    {                                                                           \
        unsigned int cnt = cl[lane++];                                          \
        float v = v4.F, w = w4.F;                                               \
        float ge = ge4.F + Qe4.F * (float)(cnt & 0xffffu);                      \
        float gi = gi4.F + Qi4.F * (float)(cnt >> 16);                          \
        float gl = gl4.F, dT = dT4.F, vr = vr4.F;                               \
        float I = Ib4.F + ssc4.F * st4.F + ge * (Ege4.F - v) + gi * (Egi4.F - v); \
        float exp_term = gl * dT * expf(fminf((v - vt4.F) / dT, 20.0f));        \
        float dv = (-gl * (v - vr) + exp_term - w + I) / C4.F;                  \
        float dw = (-w + a4.F * (v - vr)) / tw4.F;                              \
        float refr = rf4.F;                                                     \
        float vn = (refr <= 0.0f) ? (v + dv * dt) : v;                          \
        float wn = w + dw * dt;                                                 \
        geo.F = ge - (ge / tge4.F) * dt;                                        \
        gio.F = gi - (gi / tgi4.F) * dt;                                        \
        bool spk = vn > vc4.F;                                                  \
        vo.F = spk ? vrs4.F : vn;                                               \
        wo.F = spk ? (wn + b4.F) : wn;                                          \
        ro.F = (spk ? tr4.F : refr) - dt;                                       \
        so.F = spk ? 1.0f : 0.0f;                                               \
    }
    LANE(x) LANE(y) LANE(z) LANE(w)
#undef LANE

    *reinterpret_cast<float4*>(out + 0 * n + i * 4) = vo;
    *reinterpret_cast<float4*>(out + 1 * n + i * 4) = wo;
    *reinterpret_cast<float4*>(out + 2 * n + i * 4) = geo;
    *reinterpret_cast<float4*>(out + 3 * n + i * 4) = gio;
    *reinterpret_cast<float4*>(out + 4 * n + i * 4) = ro;
    *reinterpret_cast<float4*>(out + 5 * n + i * 4) = so;
}

extern "C" void kernel_launch(void* const* d_in, const int* in_sizes, int n_in,
                              void* d_out, int out_size) {
    const float* voltage    = (const float*)d_in[0];
    const float* adapt      = (const float*)d_in[1];
    const float* ge         = (const float*)d_in[2];
    const float* gi         = (const float*)d_in[3];
    const float* stim       = (const float*)d_in[4];
    const float* refr       = (const float*)d_in[5];
    const float* g_L        = (const float*)d_in[6];
    const float* delta_T    = (const float*)d_in[7];
    const float* v_thresh   = (const float*)d_in[8];
    const float* v_rest     = (const float*)d_in[9];
    const float* C          = (const float*)d_in[10];
    const float* a          = (const float*)d_in[11];
    const float* b          = (const float*)d_in[12];
    const float* tau_w      = (const float*)d_in[13];
    const float* tau_ge     = (const float*)d_in[14];
    const float* tau_gi     = (const float*)d_in[15];
    const float* E_ge       = (const float*)d_in[16];
    const float* E_gi       = (const float*)d_in[17];
    const float* I_bias     = (const float*)d_in[18];
    const float* stim_scale = (const float*)d_in[19];
    const float* Q_ge       = (const float*)d_in[20];
    const float* Q_gi       = (const float*)d_in[21];
    const float* v_cut      = (const float*)d_in[22];
    const float* v_reset    = (const float*)d_in[23];
    const float* t_refrac   = (const float*)d_in[24];
    const float* spiked     = (const float*)d_in[25];
    const float* is_exc     = (const float*)d_in[26];
    const int*   edge_index = (const int*)d_in[27];
    const float* dt         = (const float*)d_in[28];

    int n = in_sizes[0];
    int n4 = n / 4;
    int E = in_sizes[27] / 2;
    const int* src = edge_index;
    const int* dst = edge_index + E;

    build_mask_kernel<<<(n + 255) / 256, 256>>>(spiked, is_exc, n);

    // PDL attribute: secondary may launch before primary completes; ordering
    // is enforced by cudaGridDependencySynchronize() inside the kernels.
    cudaLaunchAttribute pdl[1];
    pdl[0].id = cudaLaunchAttributeProgrammaticStreamSerialization;
    pdl[0].val.programmaticStreamSerializationAllowed = 1;

    {
        cudaLaunchConfig_t cfg = {};
        int edge_blocks = (E + EDGE_PER_BLOCK - 1) / EDGE_PER_BLOCK;
        cfg.gridDim  = dim3(edge_blocks, 1, 1);
        cfg.blockDim = dim3(EDGE_BLOCK, 1, 1);
        cfg.attrs = pdl;
        cfg.numAttrs = 1;
        cudaLaunchKernelEx(&cfg, edge_kernel, src, dst, E);
    }

    {
        cudaLaunchConfig_t cfg = {};
        cfg.gridDim  = dim3((n4 + 127) / 128, 1, 1);
        cfg.blockDim = dim3(128, 1, 1);
        cfg.attrs = pdl;
        cfg.numAttrs = 1;
        cudaLaunchKernelEx(&cfg, neuron_kernel,
            (const float4*)voltage, (const float4*)adapt,
            (const float4*)ge, (const float4*)gi,
            (const float4*)stim, (const float4*)refr,
            (const float4*)g_L, (const float4*)delta_T,
            (const float4*)v_thresh, (const float4*)v_rest,
            (const float4*)C, (const float4*)a, (const float4*)b,
            (const float4*)tau_w, (const float4*)tau_ge, (const float4*)tau_gi,
            (const float4*)E_ge, (const float4*)E_gi,
            (const float4*)I_bias, (const float4*)stim_scale,
            (const float4*)Q_ge, (const float4*)Q_gi,
            (const float4*)v_cut, (const float4*)v_reset, (const float4*)t_refrac,
            dt, (float*)d_out, n4);
    }
}

// round 15
// speedup vs baseline: 1.2058x; 1.0960x over previous
#include <cuda_runtime.h>
#include <cuda_bf16.h>

// Problem constants (fixed by dataset): N = 131072 neurons, E = N*64 edges.
#define MAX_N 131072
#define NWORDS (MAX_N / 32)     // 4096 words = 16 KB per bitmask

// Scratch: zero-initialized at load; neuron kernel consumes AND re-zeros so
// every graph replay starts clean (deterministic).
// Packed event counts: low 16 bits = excitatory arrivals, high 16 = inhibitory.
__device__ unsigned int g_cnt[MAX_N];
// Bit-planar spike tables: 1 bit/neuron.
__device__ unsigned int g_act[NWORDS];   // neuron spiked last step
__device__ unsigned int g_exc[NWORDS];   // spiked AND excitatory

// ---------------------------------------------------------------------------
// Kernel 1: build bitmasks. float4 loads (4 neurons/thread, best-measured
// variant), nibble -> word via 3-round shfl-OR, 1 store per 8 threads.
// Bool inputs arrive as float32 (0.0 / 1.0).
// ---------------------------------------------------------------------------
__global__ void build_mask_kernel(const float4* __restrict__ spiked4,
                                  const float4* __restrict__ is_exc4,
                                  int n4) {
    int i = blockIdx.x * blockDim.x + threadIdx.x;
    if (i >= n4) return;
    float4 s = spiked4[i];
    float4 x = is_exc4[i];
    unsigned int a = 0, e = 0;
    if (s.x != 0.0f) { a |= 1u; if (x.x != 0.0f) e |= 1u; }
    if (s.y != 0.0f) { a |= 2u; if (x.y != 0.0f) e |= 2u; }
    if (s.z != 0.0f) { a |= 4u; if (x.z != 0.0f) e |= 4u; }
    if (s.w != 0.0f) { a |= 8u; if (x.w != 0.0f) e |= 8u; }
    unsigned int sh = (i & 7) * 4;
    a <<= sh;
    e <<= sh;
#pragma unroll
    for (int o = 1; o < 8; o <<= 1) {
        a |= __shfl_xor_sync(0xffffffffu, a, o);
        e |= __shfl_xor_sync(0xffffffffu, e, o);
    }
    if ((i & 7) == 0) {
        g_act[i >> 3] = a;
        g_exc[i >> 3] = e;
    }
}

// ---------------------------------------------------------------------------
// Kernel 2: event-driven synaptic scatter (PDL secondary of build_mask).
// R9-proven: 32768 edges/block in 2 rounds of 4 int4 src groups/thread,
// 2 CTAs/SM. Round-0 src front-batched BEFORE cudaGridDependencySynchronize.
// 16 KB act + 16 KB exc bitmasks staged in smem; dst int4 loaded only for
// groups with an active source; one packed-int atomic per active edge.
// ---------------------------------------------------------------------------
#define EDGE_BLOCK  1024
#define EDGE_GPT    4                               // int4 groups per round
#define EDGE_ROUNDS 2
#define EDGE_PER_BLOCK (EDGE_BLOCK * EDGE_GPT * 4 * EDGE_ROUNDS)  // 32768

__global__ void __launch_bounds__(EDGE_BLOCK, 2)
edge_kernel(const int* __restrict__ src,
            const int* __restrict__ dst,
            int E) {
    __shared__ unsigned int s_act[NWORDS];   // 16 KB
    __shared__ unsigned int s_exc[NWORDS];   // 16 KB

    const int tid = threadIdx.x;
    long base = (long)blockIdx.x * EDGE_PER_BLOCK;
    bool full = (base + EDGE_PER_BLOCK) <= (long)E;

    const int4* src4 = reinterpret_cast<const int4*>(src + base);
    const int4* dst4 = reinterpret_cast<const int4*>(dst + base);

    // ---- pre-dependency: front-batch round-0 src (independent of build) ----
    int4 sb[EDGE_GPT];
    if (full) {
#pragma unroll
        for (int k = 0; k < EDGE_GPT; k++)
            sb[k] = src4[tid + k * EDGE_BLOCK];
    }

    // ---- wait for build_mask results, then stage tables ----
    cudaGridDependencySynchronize();
    {
        const uint4* ga = reinterpret_cast<const uint4*>(g_act);
        const uint4* gx = reinterpret_cast<const uint4*>(g_exc);
        reinterpret_cast<uint4*>(s_act)[tid] = ga[tid];
        reinterpret_cast<uint4*>(s_exc)[tid] = gx[tid];
    }
    __syncthreads();

    if (full) {
#pragma unroll
        for (int r = 0; r < EDGE_ROUNDS; r++) {
            if (r > 0) {
#pragma unroll
                for (int k = 0; k < EDGE_GPT; k++)
                    sb[k] = src4[tid + (r * EDGE_GPT + k) * EDGE_BLOCK];
            }
#pragma unroll
            for (int k = 0; k < EDGE_GPT; k++) {
                int ss[4] = {sb[k].x, sb[k].y, sb[k].z, sb[k].w};
                unsigned int aa[4];
                unsigned int any = 0;
#pragma unroll
                for (int j = 0; j < 4; j++) {
                    aa[j] = (s_act[ss[j] >> 5] >> (ss[j] & 31)) & 1u;
                    any |= aa[j];
                }
                if (any) {
                    int4 d4 = dst4[tid + (r * EDGE_GPT + k) * EDGE_BLOCK];
                    int dd[4] = {d4.x, d4.y, d4.z, d4.w};
#pragma unroll
                    for (int j = 0; j < 4; j++) {
                        if (aa[j]) {
                            int idx = ss[j];
                            bool e = (s_exc[idx >> 5] >> (idx & 31)) & 1u;
                            atomicAdd(&g_cnt[dd[j]], e ? 1u : 65536u);
                        }
                    }
                }
            }
        }
    } else {
        for (long e = base + tid; e < E; e += EDGE_BLOCK) {
            int idx = src[e];
            if ((s_act[idx >> 5] >> (idx & 31)) & 1u) {
                bool ex = (s_exc[idx >> 5] >> (idx & 31)) & 1u;
                atomicAdd(&g_cnt[dst[e]], ex ? 1u : 65536u);
            }
        }
    }
}

// ---------------------------------------------------------------------------
// Kernel 3: AdEx neuron update, float4-vectorized (PDL secondary of edge).
// SPLIT prefetch: the state streams (voltage/adapt/ge/gi/Q/stim/refr) are
// loaded BEFORE the dependency sync (overlap with edge tail); the 13 pure
// parameter streams load after it (fewer live regs across the sync -> higher
// occupancy than full prefetch, more overlap than sync-first).
// ge += Q_ge * exc_count ; gi += Q_gi * inh_count  (Q read coalesced here).
// ---------------------------------------------------------------------------
__global__ void neuron_kernel(
    const float4* __restrict__ voltage, const float4* __restrict__ adapt,
    const float4* __restrict__ ge_in,   const float4* __restrict__ gi_in,
    const float4* __restrict__ stim,    const float4* __restrict__ refr_in,
    const float4* __restrict__ g_L,     const float4* __restrict__ delta_T,
    const float4* __restrict__ v_thresh,const float4* __restrict__ v_rest,
    const float4* __restrict__ Cm,      const float4* __restrict__ aa,
    const float4* __restrict__ bb,      const float4* __restrict__ tau_w,
    const float4* __restrict__ tau_ge,  const float4* __restrict__ tau_gi,
    const float4* __restrict__ E_ge,    const float4* __restrict__ E_gi,
    const float4* __restrict__ I_bias,  const float4* __restrict__ stim_scale,
    const float4* __restrict__ Qge,     const float4* __restrict__ Qgi,
    const float4* __restrict__ v_cut,   const float4* __restrict__ v_reset,
    const float4* __restrict__ t_refrac,
    const float* __restrict__ dt_ptr,
    float* __restrict__ out, int n4) {
    int i = blockIdx.x * blockDim.x + threadIdx.x;
    if (i >= n4) { cudaGridDependencySynchronize(); return; }
    int n = n4 * 4;

    // ---- pre-dependency: state streams only (bounded register cost) ----
    float dt = __ldg(dt_ptr);
    float4 v4  = voltage[i];
    float4 w4  = adapt[i];
    float4 ge4 = ge_in[i];
    float4 gi4 = gi_in[i];
    float4 Qe4 = Qge[i];
    float4 Qi4 = Qgi[i];
    float4 st4 = stim[i];
    float4 rf4 = refr_in[i];

    // ---- wait for edge atomics, consume + re-zero counts ----
    cudaGridDependencySynchronize();
    uint4 c4 = *reinterpret_cast<const uint4*>(g_cnt + i * 4);
    *reinterpret_cast<uint4*>(g_cnt + i * 4) = make_uint4(0u, 0u, 0u, 0u);
    unsigned int cl[4] = {c4.x, c4.y, c4.z, c4.w};

    // ---- post-sync: parameter streams ----
    float4 gl4 = g_L[i];
    float4 dT4 = delta_T[i];
    float4 vt4 = v_thresh[i];
    float4 vr4 = v_rest[i];
    float4 C4  = Cm[i];
    float4 a4  = aa[i];
    float4 b4  = bb[i];
    float4 tw4 = tau_w[i];
    float4 tge4 = tau_ge[i];
    float4 tgi4 = tau_gi[i];
    float4 Ege4 = E_ge[i];
    float4 Egi4 = E_gi[i];
    float4 Ib4  = I_bias[i];
    float4 ssc4 = stim_scale[i];
    float4 vc4  = v_cut[i];
    float4 vrs4 = v_reset[i];
    float4 tr4  = t_refrac[i];

    float4 vo, wo, geo, gio, ro, so;
    int lane = 0;

#define LANE(F)                                                                 \
    {                                                                           \
        unsigned int cnt = cl[lane++];                                          \
        float v = v4.F, w = w4.F;                                               \
        float ge = ge4.F + Qe4.F * (float)(cnt & 0xffffu);                      \
        float gi = gi4.F + Qi4.F * (float)(cnt >> 16);                          \
        float gl = gl4.F, dT = dT4.F, vr = vr4.F;                               \
        float I = Ib4.F + ssc4.F * st4.F + ge * (Ege4.F - v) + gi * (Egi4.F - v); \
        float exp_term = gl * dT * expf(fminf((v - vt4.F) / dT, 20.0f));        \
        float dv = (-gl * (v - vr) + exp_term - w + I) / C4.F;                  \
        float dw = (-w + a4.F * (v - vr)) / tw4.F;                              \
        float refr = rf4.F;                                                     \
        float vn = (refr <= 0.0f) ? (v + dv * dt) : v;                          \
        float wn = w + dw * dt;                                                 \
        geo.F = ge - (ge / tge4.F) * dt;                                        \
        gio.F = gi - (gi / tgi4.F) * dt;                                        \
        bool spk = vn > vc4.F;                                                  \
        vo.F = spk ? vrs4.F : vn;                                               \
        wo.F = spk ? (wn + b4.F) : wn;                                          \
        ro.F = (spk ? tr4.F : refr) - dt;                                       \
        so.F = spk ? 1.0f : 0.0f;                                               \
    }
    LANE(x) LANE(y) LANE(z) LANE(w)
#undef LANE

    *reinterpret_cast<float4*>(out + 0 * n + i * 4) = vo;
    *reinterpret_cast<float4*>(out + 1 * n + i * 4) = wo;
    *reinterpret_cast<float4*>(out + 2 * n + i * 4) = geo;
    *reinterpret_cast<float4*>(out + 3 * n + i * 4) = gio;
    *reinterpret_cast<float4*>(out + 4 * n + i * 4) = ro;
    *reinterpret_cast<float4*>(out + 5 * n + i * 4) = so;
}

extern "C" void kernel_launch(void* const* d_in, const int* in_sizes, int n_in,
                              void* d_out, int out_size) {
    const float* voltage    = (const float*)d_in[0];
    const float* adapt      = (const float*)d_in[1];
    const float* ge         = (const float*)d_in[2];
    const float* gi         = (const float*)d_in[3];
    const float* stim       = (const float*)d_in[4];
    const float* refr       = (const float*)d_in[5];
    const float* g_L        = (const float*)d_in[6];
    const float* delta_T    = (const float*)d_in[7];
    const float* v_thresh   = (const float*)d_in[8];
    const float* v_rest     = (const float*)d_in[9];
    const float* C          = (const float*)d_in[10];
    const float* a          = (const float*)d_in[11];
    const float* b          = (const float*)d_in[12];
    const float* tau_w      = (const float*)d_in[13];
    const float* tau_ge     = (const float*)d_in[14];
    const float* tau_gi     = (const float*)d_in[15];
    const float* E_ge       = (const float*)d_in[16];
    const float* E_gi       = (const float*)d_in[17];
    const float* I_bias     = (const float*)d_in[18];
    const float* stim_scale = (const float*)d_in[19];
    const float* Q_ge       = (const float*)d_in[20];
    const float* Q_gi       = (const float*)d_in[21];
    const float* v_cut      = (const float*)d_in[22];
    const float* v_reset    = (const float*)d_in[23];
    const float* t_refrac   = (const float*)d_in[24];
    const float* spiked     = (const float*)d_in[25];
    const float* is_exc     = (const float*)d_in[26];
    const int*   edge_index = (const int*)d_in[27];
    const float* dt         = (const float*)d_in[28];

    int n = in_sizes[0];
    int n4 = n / 4;
    int E = in_sizes[27] / 2;
    const int* src = edge_index;
    const int* dst = edge_index + E;

    build_mask_kernel<<<(n4 + 127) / 128, 128>>>(
        (const float4*)spiked, (const float4*)is_exc, n4);

    // PDL attribute: secondary may launch before primary completes; ordering
    // is enforced by cudaGridDependencySynchronize() inside the kernels.
    cudaLaunchAttribute pdl[1];
    pdl[0].id = cudaLaunchAttributeProgrammaticStreamSerialization;
    pdl[0].val.programmaticStreamSerializationAllowed = 1;

    {
        cudaLaunchConfig_t cfg = {};
        int edge_blocks = (E + EDGE_PER_BLOCK - 1) / EDGE_PER_BLOCK;
        cfg.gridDim  = dim3(edge_blocks, 1, 1);
        cfg.blockDim = dim3(EDGE_BLOCK, 1, 1);
        cfg.attrs = pdl;
        cfg.numAttrs = 1;
        cudaLaunchKernelEx(&cfg, edge_kernel, src, dst, E);
    }

    {
        cudaLaunchConfig_t cfg = {};
        cfg.gridDim  = dim3((n4 + 63) / 64, 1, 1);
        cfg.blockDim = dim3(64, 1, 1);
        cfg.attrs = pdl;
        cfg.numAttrs = 1;
        cudaLaunchKernelEx(&cfg, neuron_kernel,
            (const float4*)voltage, (const float4*)adapt,
            (const float4*)ge, (const float4*)gi,
            (const float4*)stim, (const float4*)refr,
            (const float4*)g_L, (const float4*)delta_T,
            (const float4*)v_thresh, (const float4*)v_rest,
            (const float4*)C, (const float4*)a, (const float4*)b,
            (const float4*)tau_w, (const float4*)tau_ge, (const float4*)tau_gi,
            (const float4*)E_ge, (const float4*)E_gi,
            (const float4*)I_bias, (const float4*)stim_scale,
            (const float4*)Q_ge, (const float4*)Q_gi,
            (const float4*)v_cut, (const float4*)v_reset, (const float4*)t_refrac,
            dt, (float*)d_out, n4);
    }
}